// round 16
// baseline (speedup 1.0000x reference)
#include <cuda_runtime.h>
#include <cuda_fp16.h>
#include <math.h>
#include <stdint.h>

// Problem constants
#define BB   2
#define SS   2048
#define MM   512
#define DD   1024
#define HH   16
#define HD   64
#define NTOK (BB*SS)        // 4096
#define MTOK (BB*MM)        // 1024
#define FF   4096           // 4*D
#define KSPLIT 4

// ---------------- scratch (device globals; no allocation) ----------------
__device__ __half g_h   [NTOK*DD];
__device__ __half g_qkv [NTOK*96];           // fused tq|ckv
__device__ float  g_part[KSPLIT*NTOK*96];    // split-K partials (fp32)
__device__ __half g_q   [NTOK*DD];
__device__ __half g_kvs [NTOK*2048];         // fused k|v
__device__ __half g_o   [NTOK*DD];
__device__ float  g_x1  [NTOK*DD];           // residual stream fp32
__device__ __half g_h2  [NTOK*DD];
__device__ __half g_qc  [NTOK*DD];
__device__ __half g_kv2 [MTOK*2048];         // fused kc|vc
__device__ __half g_oc  [NTOK*DD];
__device__ float  g_x2  [NTOK*DD];           // residual stream fp32
__device__ __half g_h3  [NTOK*DD];
__device__ __half g_act [NTOK*FF];           // silu(gate)*up (fused epilogue)
__device__ __half g_mem [MTOK*DD];

// fp16 transposed weights: Wt[N][K]
__device__ __half gw_qkv   [96*DD];
__device__ __half gw_uq    [DD*32];
__device__ __half gw_ukuv  [2048*64];
__device__ __half gw_oself [DD*DD];
__device__ __half gw_qc    [DD*DD];
__device__ __half gw_kcvc  [2048*DD];
__device__ __half gw_oc    [DD*DD];
__device__ __half gw_gateup[(2*FF)*DD];      // INTERLEAVED: row 2j=gate_j, 2j+1=up_j
__device__ __half gw_down  [DD*FF];

// ---------------- fused weight convert+transpose ----------------
struct WDesc { const float* src; __half* dst; int K; int N; int tile0; int rowMul; int rowOff; };
struct WTable { WDesc w[13]; };

__global__ void convert_all_kernel(WTable t) {
    __shared__ float tl[32][33];
    int bid = blockIdx.x;
    int wi = 0;
    #pragma unroll
    for (int i = 1; i < 13; i++) if (bid >= t.w[i].tile0) wi = i;
    const WDesc d = t.w[wi];
    int lt = bid - d.tile0;
    int ntiles_n = d.N >> 5;
    int n0 = (lt % ntiles_n) * 32;
    int k0 = (lt / ntiles_n) * 32;
    int tx = threadIdx.x & 31, ty = threadIdx.x >> 5;
    #pragma unroll
    for (int i = 0; i < 4; i++) {
        int k = k0 + ty + i * 8;
        tl[ty + i * 8][tx] = d.src[(size_t)k * d.N + n0 + tx];
    }
    __syncthreads();
    #pragma unroll
    for (int i = 0; i < 4; i++) {
        int n = n0 + ty + i * 8;
        d.dst[(size_t)(d.rowMul * n + d.rowOff) * d.K + k0 + tx] = __float2half_rn(tl[tx][ty + i * 8]);
    }
}

__global__ void round_copy_kernel(const float* __restrict__ in, __half* __restrict__ out, int n) {
    int i = blockIdx.x * blockDim.x + threadIdx.x;
    if (i < n) out[i] = __float2half_rn(in[i]);
}

// ---------------- split-K reduce for fused qkv ----------------
__global__ void reduce_qkv_kernel(const float* __restrict__ part, __half* __restrict__ qkv) {
    int i = blockIdx.x * 256 + threadIdx.x;
    float s = 0.f;
    #pragma unroll
    for (int z = 0; z < KSPLIT; z++) s += part[(size_t)z * NTOK * 96 + i];
    qkv[i] = __float2half_rn(s);
}

// ---------------- rmsnorm (fp16 out, float4 loads; D=1024, 256 thr) ----------------
__global__ void rmsnorm_kernel(const float* __restrict__ x, const float* __restrict__ w,
                               __half* __restrict__ out, int D) {
    int row = blockIdx.x;
    const float4* xr = (const float4*)(x + (size_t)row * D);
    float4 v = xr[threadIdx.x];
    __shared__ float red[256];
    float s = v.x * v.x + v.y * v.y + v.z * v.z + v.w * v.w;
    red[threadIdx.x] = s; __syncthreads();
    for (int st = 128; st > 0; st >>= 1) {
        if (threadIdx.x < st) red[threadIdx.x] += red[threadIdx.x + st];
        __syncthreads();
    }
    float inv = rsqrtf(red[0] / (float)D + 1e-6f);
    float4 wv = ((const float4*)w)[threadIdx.x];
    __half2 h0 = __floats2half2_rn(v.x * inv * wv.x, v.y * inv * wv.y);
    __half2 h1 = __floats2half2_rn(v.z * inv * wv.z, v.w * inv * wv.w);
    __half2* op = (__half2*)(out + (size_t)row * D) + threadIdx.x * 2;
    op[0] = h0; op[1] = h1;
}

// ---------------- fp16 MMA + ldmatrix helpers ----------------
__device__ __forceinline__ void mma16816h(float* c, const uint32_t* a, const uint32_t* b) {
    asm volatile(
        "mma.sync.aligned.m16n8k16.row.col.f32.f16.f16.f32 "
        "{%0,%1,%2,%3}, {%4,%5,%6,%7}, {%8,%9}, {%0,%1,%2,%3};\n"
        : "+f"(c[0]), "+f"(c[1]), "+f"(c[2]), "+f"(c[3])
        : "r"(a[0]), "r"(a[1]), "r"(a[2]), "r"(a[3]), "r"(b[0]), "r"(b[1]));
}

__device__ __forceinline__ void ldsm4(uint32_t* r, uint32_t addr) {
    asm volatile("ldmatrix.sync.aligned.m8n8.x4.shared.b16 {%0,%1,%2,%3}, [%4];"
                 : "=r"(r[0]), "=r"(r[1]), "=r"(r[2]), "=r"(r[3]) : "r"(addr));
}

__device__ __forceinline__ void ldsm4t(uint32_t* r, uint32_t addr) {
    asm volatile("ldmatrix.sync.aligned.m8n8.x4.trans.shared.b16 {%0,%1,%2,%3}, [%4];"
                 : "=r"(r[0]), "=r"(r[1]), "=r"(r[2]), "=r"(r[3]) : "r"(addr));
}

__device__ __forceinline__ void cpasync16(uint32_t dst, const void* src) {
    asm volatile("cp.async.cg.shared.global [%0], [%1], 16;\n" :: "r"(dst), "l"(src));
}

__device__ __forceinline__ float sigmoidf_(float v) { return 1.f / (1.f + __expf(-v)); }

#define LDH 40                  // smem row stride in halves (80B, conflict-free)
#define H_ST (128 * LDH)        // halves per tensor per stage (5120)
#define STG 4
#define TG_SMEM (STG * 2 * H_ST * 2)   // 81920 B

// ================ fp16 tensor GEMM: 128x128 tile, BK=32, cp.async 4-stage ====
// mode 0: Cf fp32 (+R); mode 1: Ch fp16; mode 2: fused silu-pair -> Ch fp16 [M][N/2]
__global__ __launch_bounds__(256)
void hgemm_kernel(const __half* __restrict__ A, int lda,
                  const __half* __restrict__ Wt, int ldb,
                  const float* __restrict__ R, float* __restrict__ Cf,
                  __half* __restrict__ Ch, int M, int N, int K, int mode) {
    extern __shared__ __half hsm[];
    __half* As = hsm;
    __half* Bs = hsm + STG * H_ST;

    int tid = threadIdx.x;
    int lane = tid & 31, warp = tid >> 5;
    int wm = warp & 1, wn = warp >> 1;          // 2 x 4 warps: 64 x 32 each
    int bm = blockIdx.y * 128, bn = blockIdx.x * 128;
    int kz = blockIdx.z;

    float acc[4][4][4] = {};

    int ld_row = tid >> 1;
    int gsel = (tid & 1) * 16;

    int nc = K / 32;

    const __half* aRow = A + (size_t)(bm + ld_row) * lda + kz * K + gsel;
    int nIdx = bn + ld_row;
    if (nIdx >= N) nIdx = N - 1;
    const __half* bRow = Wt + (size_t)nIdx * ldb + kz * K + gsel;
    uint32_t aD = (uint32_t)__cvta_generic_to_shared(As + ld_row * LDH + gsel);
    uint32_t bD = (uint32_t)__cvta_generic_to_shared(Bs + ld_row * LDH + gsel);

    uint32_t aBase0 = (uint32_t)__cvta_generic_to_shared(As) +
        ((uint32_t)(wm * 64 + (lane & 15)) * LDH + (uint32_t)((lane >> 4) * 8)) * 2;
    uint32_t bBase0 = (uint32_t)__cvta_generic_to_shared(Bs) +
        ((uint32_t)(wn * 32 + ((lane >> 4) << 3) + (lane & 7)) * LDH +
         (uint32_t)(((lane >> 3) & 1) * 8)) * 2;

    #pragma unroll
    for (int s = 0; s < 3; s++) {
        if (s < nc) {
            int k0 = s * 32;
            cpasync16(aD + s * H_ST * 2,      aRow + k0);
            cpasync16(aD + s * H_ST * 2 + 16, aRow + k0 + 8);
            cpasync16(bD + s * H_ST * 2,      bRow + k0);
            cpasync16(bD + s * H_ST * 2 + 16, bRow + k0 + 8);
        }
        asm volatile("cp.async.commit_group;\n" ::: "memory");
    }

    for (int c = 0; c < nc; c++) {
        int rem = nc - 1 - c;
        if (rem >= 2)      asm volatile("cp.async.wait_group 2;\n" ::: "memory");
        else if (rem == 1) asm volatile("cp.async.wait_group 1;\n" ::: "memory");
        else               asm volatile("cp.async.wait_group 0;\n" ::: "memory");
        __syncthreads();

        int pre = c + 3;
        if (pre < nc) {
            int s = pre % STG;
            int k0 = pre * 32;
            cpasync16(aD + s * H_ST * 2,      aRow + k0);
            cpasync16(aD + s * H_ST * 2 + 16, aRow + k0 + 8);
            cpasync16(bD + s * H_ST * 2,      bRow + k0);
            cpasync16(bD + s * H_ST * 2 + 16, bRow + k0 + 8);
            asm volatile("cp.async.commit_group;\n" ::: "memory");
        }

        uint32_t stOff = (uint32_t)(c % STG) * H_ST * 2;
        uint32_t aB = aBase0 + stOff;
        uint32_t bB = bBase0 + stOff;
        #pragma unroll
        for (int ks = 0; ks < 2; ks++) {
            uint32_t kOff = (uint32_t)ks * 32;
            uint32_t afr[4][4], bt[2][4];
            #pragma unroll
            for (int mt = 0; mt < 4; mt++)
                ldsm4(afr[mt], aB + (uint32_t)(mt * 16 * LDH) * 2 + kOff);
            #pragma unroll
            for (int qq = 0; qq < 2; qq++)
                ldsm4(bt[qq], bB + (uint32_t)(qq * 16 * LDH) * 2 + kOff);
            uint32_t bfr[4][2] = {{bt[0][0], bt[0][1]}, {bt[0][2], bt[0][3]},
                                  {bt[1][0], bt[1][1]}, {bt[1][2], bt[1][3]}};
            #pragma unroll
            for (int mt = 0; mt < 4; mt++)
                #pragma unroll
                for (int nt = 0; nt < 4; nt++)
                    mma16816h(acc[mt][nt], afr[mt], bfr[nt]);
        }
    }

    if (mode == 2) {
        int halfN = N >> 1;
        #pragma unroll
        for (int mt = 0; mt < 4; mt++) {
            int r0 = bm + wm * 64 + mt * 16 + (lane >> 2);
            #pragma unroll
            for (int nt = 0; nt < 4; nt++) {
                int cn = bn + wn * 32 + nt * 8 + (lane & 3) * 2;
                int j = cn >> 1;
                float g0 = acc[mt][nt][0], u0 = acc[mt][nt][1];
                float g1 = acc[mt][nt][2], u1 = acc[mt][nt][3];
                Ch[(size_t)r0 * halfN + j]       = __float2half_rn(g0 * sigmoidf_(g0) * u0);
                Ch[(size_t)(r0 + 8) * halfN + j] = __float2half_rn(g1 * sigmoidf_(g1) * u1);
            }
        }
        return;
    }

    float* Cz = Cf ? Cf + (size_t)kz * M * N : nullptr;
    #pragma unroll
    for (int mt = 0; mt < 4; mt++) {
        int r0 = bm + wm * 64 + mt * 16 + (lane >> 2);
        #pragma unroll
        for (int nt = 0; nt < 4; nt++) {
            int cn = bn + wn * 32 + nt * 8 + (lane & 3) * 2;
            if (cn < N) {
                float2 v0 = make_float2(acc[mt][nt][0], acc[mt][nt][1]);
                float2 v1 = make_float2(acc[mt][nt][2], acc[mt][nt][3]);
                if (Cz) {
                    if (R) {
                        float2 ra = *(const float2*)&R[(size_t)r0 * N + cn];
                        float2 rb = *(const float2*)&R[(size_t)(r0 + 8) * N + cn];
                        v0.x += ra.x; v0.y += ra.y;
                        v1.x += rb.x; v1.y += rb.y;
                    }
                    *(float2*)&Cz[(size_t)r0 * N + cn] = v0;
                    *(float2*)&Cz[(size_t)(r0 + 8) * N + cn] = v1;
                } else {
                    *(__half2*)&Ch[(size_t)r0 * N + cn] = __floats2half2_rn(v0.x, v0.y);
                    *(__half2*)&Ch[(size_t)(r0 + 8) * N + cn] = __floats2half2_rn(v1.x, v1.y);
                }
            }
        }
    }
}

// ---------------- self attention: FA2-style, register-resident softmax ----------------
// Br=128 (warp w owns rows w*16..+15, all 64 cols), Bc=64, double-buffered KV.
#define QLD 72
#define ATT_SMEM ((128*QLD + 4*64*QLD) * 2)

__global__ __launch_bounds__(256)
void self_attn_kernel(const __half* __restrict__ q, const __half* __restrict__ kvs,
                      __half* __restrict__ o) {
    extern __shared__ char smc[];
    __half* Qs  = (__half*)smc;                 // [128][72]
    __half* KV0 = Qs + 128 * QLD;               // 2 stages x (K [64][72], V [64][72])

    int qt = blockIdx.x, h = blockIdx.y, b = blockIdx.z;
    int q0 = qt * 128;
    int tid = threadIdx.x;
    int lane = tid & 31, warp = tid >> 5;

    uint32_t qsS  = (uint32_t)__cvta_generic_to_shared(Qs);
    uint32_t kv0S = (uint32_t)__cvta_generic_to_shared(KV0);

    uint32_t qBase = qsS +
        ((uint32_t)(warp * 16 + (lane & 15)) * QLD + (uint32_t)((lane >> 4) * 8)) * 2;
    uint32_t kBaseC = ((uint32_t)(((lane >> 4) << 3) + (lane & 7)) * QLD +
                      (uint32_t)(((lane >> 3) & 1) * 8)) * 2;     // + g*16*QLD*2
    uint32_t vBaseC = ((uint32_t)(lane & 15) * QLD +
                      (uint32_t)((lane >> 4) * 8)) * 2;           // + kt*16*QLD*2 + qq*32

    // Q tile + KV stage 0 via cp.async, one commit group
    const __half* qg = q + ((size_t)(b * SS + q0)) * DD + h * HD;
    #pragma unroll
    for (int i = 0; i < 4; i++) {
        int cid = i * 256 + tid;
        int r = cid >> 3, u = cid & 7;
        cpasync16(qsS + ((uint32_t)r * QLD + u * 8) * 2, qg + (size_t)r * DD + u * 8);
    }
    {
        const __half* kg = kvs + ((size_t)(b * SS)) * 2048 + h * HD;
        #pragma unroll
        for (int i = 0; i < 2; i++) {
            int cid = i * 256 + tid;
            int r = cid >> 3, u = cid & 7;
            const __half* src = kg + (size_t)r * 2048 + u * 8;
            uint32_t d = ((uint32_t)r * QLD + u * 8) * 2;
            cpasync16(kv0S + d, src);
            cpasync16(kv0S + (64 * QLD) * 2 + d, src + 1024);
        }
    }
    asm volatile("cp.async.commit_group;\n" ::: "memory");

    float mA = -INFINITY, mB = -INFINITY, lA = 0.f, lB = 0.f;
    float oacc[8][4] = {};
    int rAl = warp * 16 + (lane >> 2);          // local row of this thread (rB = +8)

    int jmax = 2 * qt + 1;
    for (int jt = 0; jt <= jmax; jt++) {
        asm volatile("cp.async.wait_group 0;\n" ::: "memory");
        __syncthreads();

        // safe prefetch of next stage (after barrier), overlaps compute below
        if (jt + 1 <= jmax) {
            int nst = (jt + 1) & 1;
            uint32_t stB = kv0S + (uint32_t)(nst * 2 * 64 * QLD) * 2;
            const __half* kg = kvs + ((size_t)(b * SS + (jt + 1) * 64)) * 2048 + h * HD;
            #pragma unroll
            for (int i = 0; i < 2; i++) {
                int cid = i * 256 + tid;
                int r = cid >> 3, u = cid & 7;
                const __half* src = kg + (size_t)r * 2048 + u * 8;
                uint32_t d = ((uint32_t)r * QLD + u * 8) * 2;
                cpasync16(stB + d, src);
                cpasync16(stB + (64 * QLD) * 2 + d, src + 1024);
            }
        }
        asm volatile("cp.async.commit_group;\n" ::: "memory");

        uint32_t stOff = (uint32_t)((jt & 1) * 2 * 64 * QLD) * 2;
        uint32_t kB = kv0S + stOff;
        uint32_t vB = kv0S + stOff + (64 * QLD) * 2;
        int kv0 = jt * 64;

        // S = Q @ K^T : 1 warp = 16 rows x 64 cols -> sacc[8][4]
        float sacc[8][4] = {};
        #pragma unroll
        for (int ks = 0; ks < 4; ks++) {
            uint32_t kOff = (uint32_t)ks * 32;
            uint32_t afr[4], bt[4][4];
            ldsm4(afr, qBase + kOff);
            #pragma unroll
            for (int g = 0; g < 4; g++)
                ldsm4(bt[g], kB + kBaseC + (uint32_t)(g * 16 * QLD) * 2 + kOff);
            #pragma unroll
            for (int g = 0; g < 4; g++) {
                uint32_t b0[2] = {bt[g][0], bt[g][1]};
                uint32_t b1[2] = {bt[g][2], bt[g][3]};
                mma16816h(sacc[2 * g],     afr, b0);
                mma16816h(sacc[2 * g + 1], afr, b1);
            }
        }

        // scale + mask (in registers)
        bool diag = (jt >= 2 * qt);
        #pragma unroll
        for (int nt = 0; nt < 8; nt++) {
            #pragma unroll
            for (int e = 0; e < 4; e++) {
                float sv = sacc[nt][e] * 0.125f;
                if (diag) {
                    int lr = rAl + (e >> 1) * 8;
                    int lc = nt * 8 + (lane & 3) * 2 + (e & 1);
                    if (kv0 + lc > q0 + lr) sv = -INFINITY;
                }
                sacc[nt][e] = sv;
            }
        }

        // register online softmax (4 lanes per row share state via shfl)
        float tmA = -INFINITY, tmB = -INFINITY;
        #pragma unroll
        for (int nt = 0; nt < 8; nt++) {
            tmA = fmaxf(tmA, fmaxf(sacc[nt][0], sacc[nt][1]));
            tmB = fmaxf(tmB, fmaxf(sacc[nt][2], sacc[nt][3]));
        }
        tmA = fmaxf(tmA, __shfl_xor_sync(0xffffffff, tmA, 1));
        tmA = fmaxf(tmA, __shfl_xor_sync(0xffffffff, tmA, 2));
        tmB = fmaxf(tmB, __shfl_xor_sync(0xffffffff, tmB, 1));
        tmB = fmaxf(tmB, __shfl_xor_sync(0xffffffff, tmB, 2));
        float nmA = fmaxf(mA, tmA), nmB = fmaxf(mB, tmB);
        float corrA = __expf(mA - nmA), corrB = __expf(mB - nmB);

        uint32_t pH[8][2];      // half2 fragments: [nt][rowA/rowB]
        float sumA = 0.f, sumB = 0.f;
        #pragma unroll
        for (int nt = 0; nt < 8; nt++) {
            float p0 = __expf(sacc[nt][0] - nmA);
            float p1 = __expf(sacc[nt][1] - nmA);
            float p2 = __expf(sacc[nt][2] - nmB);
            float p3 = __expf(sacc[nt][3] - nmB);
            sumA += p0 + p1; sumB += p2 + p3;
            __half2 hA = __floats2half2_rn(p0, p1);
            __half2 hB = __floats2half2_rn(p2, p3);
            pH[nt][0] = *(uint32_t*)&hA;
            pH[nt][1] = *(uint32_t*)&hB;
        }
        sumA += __shfl_xor_sync(0xffffffff, sumA, 1);
        sumA += __shfl_xor_sync(0xffffffff, sumA, 2);
        sumB += __shfl_xor_sync(0xffffffff, sumB, 1);
        sumB += __shfl_xor_sync(0xffffffff, sumB, 2);
        lA = lA * corrA + sumA;  mA = nmA;
        lB = lB * corrB + sumB;  mB = nmB;

        #pragma unroll
        for (int nt = 0; nt < 8; nt++) {
            oacc[nt][0] *= corrA; oacc[nt][1] *= corrA;
            oacc[nt][2] *= corrB; oacc[nt][3] *= corrB;
        }

        // O += P @ V : P fragments from registers, V via ldmatrix.trans
        #pragma unroll
        for (int kt = 0; kt < 4; kt++) {
            uint32_t afr[4] = {pH[2 * kt][0], pH[2 * kt][1],
                               pH[2 * kt + 1][0], pH[2 * kt + 1][1]};
            uint32_t bt[4][4];
            #pragma unroll
            for (int qq = 0; qq < 4; qq++)
                ldsm4t(bt[qq], vB + vBaseC + (uint32_t)(kt * 16 * QLD) * 2 + (uint32_t)qq * 32);
            #pragma unroll
            for (int qq = 0; qq < 4; qq++) {
                uint32_t b0[2] = {bt[qq][0], bt[qq][1]};
                uint32_t b1[2] = {bt[qq][2], bt[qq][3]};
                mma16816h(oacc[2 * qq],     afr, b0);
                mma16816h(oacc[2 * qq + 1], afr, b1);
            }
        }
    }

    // epilogue
    {
        float iA = 1.f / lA, iB = 1.f / lB;
        int rA = q0 + rAl;
        #pragma unroll
        for (int nt = 0; nt < 8; nt++) {
            int c0 = nt * 8 + (lane & 3) * 2;
            size_t ra = ((size_t)(b * SS + rA)) * DD + h * HD + c0;
            size_t rb = ((size_t)(b * SS + rA + 8)) * DD + h * HD + c0;
            *(__half2*)&o[ra] = __floats2half2_rn(oacc[nt][0] * iA, oacc[nt][1] * iA);
            *(__half2*)&o[rb] = __floats2half2_rn(oacc[nt][2] * iB, oacc[nt][3] * iB);
        }
    }
}

// ---------------- cross attention (windowed, <=9 keys), fp16 in/out ----------------
__global__ void cross_attn_kernel(const __half* __restrict__ qc, const __half* __restrict__ kv2,
                                  const int* __restrict__ seg_ids, __half* __restrict__ oc) {
    int n = blockIdx.x;
    int warp = threadIdx.x / 32;
    int lane = threadIdx.x % 32;
    int h = blockIdx.y * 4 + warp;
    int b = n / SS;
    int seg = seg_ids[n];
    int jlo = seg - 8; if (jlo < 0) jlo = 0;
    int cnt = seg - jlo + 1;

    const __half* qv = qc + (size_t)n * DD + h * HD;
    float q0v = __half2float(qv[lane]), q1v = __half2float(qv[lane + 32]);

    float sc[9];
    float mx = -INFINITY;
    for (int t = 0; t < cnt; t++) {
        const __half* kv = kv2 + ((size_t)(b * MM + jlo + t)) * 2048 + h * HD;
        float p = q0v * __half2float(kv[lane]) + q1v * __half2float(kv[lane + 32]);
        #pragma unroll
        for (int off = 16; off > 0; off >>= 1)
            p += __shfl_xor_sync(0xffffffff, p, off);
        p *= 0.125f;
        sc[t] = p;
        mx = fmaxf(mx, p);
    }
    float sum = 0.f;
    for (int t = 0; t < cnt; t++) { sc[t] = __expf(sc[t] - mx); sum += sc[t]; }
    float o0 = 0.f, o1 = 0.f;
    for (int t = 0; t < cnt; t++) {
        const __half* vv = kv2 + ((size_t)(b * MM + jlo + t)) * 2048 + 1024 + h * HD;
        o0 += sc[t] * __half2float(vv[lane]);
        o1 += sc[t] * __half2float(vv[lane + 32]);
    }
    float inv = 1.f / sum;
    oc[(size_t)n * DD + h * HD + lane]      = __float2half_rn(o0 * inv);
    oc[(size_t)n * DD + h * HD + lane + 32] = __float2half_rn(o1 * inv);
}

// ---------------- launch ----------------
extern "C" void kernel_launch(void* const* d_in, const int* in_sizes, int n_in,
                              void* d_out, int out_size) {
    const float* x        = (const float*)d_in[0];
    const float* memory   = (const float*)d_in[1];
    const int*   seg_ids  = (const int*)  d_in[2];
    const float* norm1_w  = (const float*)d_in[3];
    const float* W_dq     = (const float*)d_in[4];
    const float* W_uq     = (const float*)d_in[5];
    const float* W_dkv    = (const float*)d_in[6];
    const float* W_uk     = (const float*)d_in[7];
    const float* W_uv     = (const float*)d_in[8];
    const float* W_o_self = (const float*)d_in[9];
    const float* norm2_w  = (const float*)d_in[10];
    const float* W_q_c    = (const float*)d_in[11];
    const float* W_k_c    = (const float*)d_in[12];
    const float* W_v_c    = (const float*)d_in[13];
    const float* W_o_c    = (const float*)d_in[14];
    const float* norm3_w  = (const float*)d_in[15];
    const float* W_gate   = (const float*)d_in[16];
    const float* W_up     = (const float*)d_in[17];
    const float* W_down   = (const float*)d_in[18];
    float* out = (float*)d_out;

    __half *h, *qkv, *q, *kvs, *o, *h2, *qc, *kv2, *oc, *h3, *act, *mem;
    float *part, *x1, *x2;
    cudaGetSymbolAddress((void**)&h,    g_h);
    cudaGetSymbolAddress((void**)&qkv,  g_qkv);
    cudaGetSymbolAddress((void**)&part, g_part);
    cudaGetSymbolAddress((void**)&q,    g_q);
    cudaGetSymbolAddress((void**)&kvs,  g_kvs);
    cudaGetSymbolAddress((void**)&o,    g_o);
    cudaGetSymbolAddress((void**)&x1,   g_x1);
    cudaGetSymbolAddress((void**)&h2,   g_h2);
    cudaGetSymbolAddress((void**)&qc,   g_qc);
    cudaGetSymbolAddress((void**)&kv2,  g_kv2);
    cudaGetSymbolAddress((void**)&oc,   g_oc);
    cudaGetSymbolAddress((void**)&x2,   g_x2);
    cudaGetSymbolAddress((void**)&h3,   g_h3);
    cudaGetSymbolAddress((void**)&act,  g_act);
    cudaGetSymbolAddress((void**)&mem,  g_mem);

    __half *w_qkv, *w_uq, *w_ukuv, *w_oself, *w_qc, *w_kcvc, *w_oc, *w_gateup, *w_down;
    cudaGetSymbolAddress((void**)&w_qkv,    gw_qkv);
    cudaGetSymbolAddress((void**)&w_uq,     gw_uq);
    cudaGetSymbolAddress((void**)&w_ukuv,   gw_ukuv);
    cudaGetSymbolAddress((void**)&w_oself,  gw_oself);
    cudaGetSymbolAddress((void**)&w_qc,     gw_qc);
    cudaGetSymbolAddress((void**)&w_kcvc,   gw_kcvc);
    cudaGetSymbolAddress((void**)&w_oc,     gw_oc);
    cudaGetSymbolAddress((void**)&w_gateup, gw_gateup);
    cudaGetSymbolAddress((void**)&w_down,   gw_down);

    WTable wt;
    const float* srcs[13] = {W_dq, W_uq, W_dkv, W_uk, W_uv, W_o_self, W_q_c, W_k_c, W_v_c,
                             W_o_c, W_gate, W_up, W_down};
    __half* dsts[13] = {w_qkv, w_uq, w_qkv + 32 * DD, w_ukuv, w_ukuv + 1024 * 64, w_oself, w_qc,
                        w_kcvc, w_kcvc + 1024 * DD, w_oc, w_gateup, w_gateup, w_down};
    int Ks[13]  = {DD, 32, DD, 64, 64, DD, DD, DD, DD, DD, DD, DD, FF};
    int Ns[13]  = {32, DD, 64, DD, DD, DD, DD, DD, DD, DD, FF, FF, DD};
    int rm[13]  = {1, 1, 1, 1, 1, 1, 1, 1, 1, 1, 2, 2, 1};
    int ro[13]  = {0, 0, 0, 0, 0, 0, 0, 0, 0, 0, 0, 1, 0};
    int tot = 0;
    for (int i = 0; i < 13; i++) {
        wt.w[i].src = srcs[i]; wt.w[i].dst = dsts[i];
        wt.w[i].K = Ks[i]; wt.w[i].N = Ns[i];
        wt.w[i].tile0 = tot;
        wt.w[i].rowMul = rm[i]; wt.w[i].rowOff = ro[i];
        tot += (Ks[i] / 32) * (Ns[i] / 32);
    }
    convert_all_kernel<<<tot, 256>>>(wt);
    round_copy_kernel<<<(MTOK * DD + 255) / 256, 256>>>(memory, mem, MTOK * DD);

    cudaFuncSetAttribute(hgemm_kernel, cudaFuncAttributeMaxDynamicSharedMemorySize, TG_SMEM);
    cudaFuncSetAttribute(self_attn_kernel, cudaFuncAttributeMaxDynamicSharedMemorySize, ATT_SMEM);

    // ---- Phase 1: MLA self-attention ----
    rmsnorm_kernel<<<NTOK, 256>>>(x, norm1_w, h, DD);
    hgemm_kernel<<<dim3(1, NTOK / 128, KSPLIT), 256, TG_SMEM>>>(h, DD, w_qkv, DD, nullptr, part,
                                                                nullptr, NTOK, 96, DD / KSPLIT, 0);
    reduce_qkv_kernel<<<NTOK * 96 / 256, 256>>>(part, qkv);
    hgemm_kernel<<<dim3(DD / 128, NTOK / 128), 256, TG_SMEM>>>(qkv, 96, w_uq, 32, nullptr, nullptr,
                                                               q, NTOK, DD, 32, 1);
    hgemm_kernel<<<dim3(2048 / 128, NTOK / 128), 256, TG_SMEM>>>(qkv + 32, 96, w_ukuv, 64, nullptr,
                                                                 nullptr, kvs, NTOK, 2048, 64, 1);
    self_attn_kernel<<<dim3(SS / 128, HH, BB), 256, ATT_SMEM>>>(q, kvs, o);
    hgemm_kernel<<<dim3(DD / 128, NTOK / 128), 256, TG_SMEM>>>(o, DD, w_oself, DD, x, x1,
                                                               nullptr, NTOK, DD, DD, 0);

    // ---- Phase 2: windowed cross-attention ----
    rmsnorm_kernel<<<NTOK, 256>>>(x1, norm2_w, h2, DD);
    hgemm_kernel<<<dim3(DD / 128, NTOK / 128), 256, TG_SMEM>>>(h2, DD, w_qc, DD, nullptr, nullptr,
                                                               qc, NTOK, DD, DD, 1);
    hgemm_kernel<<<dim3(2048 / 128, MTOK / 128), 256, TG_SMEM>>>(mem, DD, w_kcvc, DD, nullptr,
                                                                 nullptr, kv2, MTOK, 2048, DD, 1);
    cross_attn_kernel<<<dim3(NTOK, 4), 128>>>(qc, kv2, seg_ids, oc);
    hgemm_kernel<<<dim3(DD / 128, NTOK / 128), 256, TG_SMEM>>>(oc, DD, w_oc, DD, x1, x2,
                                                               nullptr, NTOK, DD, DD, 0);

    // ---- Phase 3: SwiGLU MLP (silu fused into gate/up GEMM epilogue) ----
    rmsnorm_kernel<<<NTOK, 256>>>(x2, norm3_w, h3, DD);
    hgemm_kernel<<<dim3((2 * FF) / 128, NTOK / 128), 256, TG_SMEM>>>(h3, DD, w_gateup, DD, nullptr,
                                                                     nullptr, act, NTOK, 2 * FF, DD, 2);
    hgemm_kernel<<<dim3(DD / 128, NTOK / 128), 256, TG_SMEM>>>(act, FF, w_down, FF, x2, out,
                                                               nullptr, NTOK, DD, FF, 0);
}

// round 17
// speedup vs baseline: 1.3427x; 1.3427x over previous
#include <cuda_runtime.h>
#include <cuda_fp16.h>
#include <math.h>
#include <stdint.h>

// Problem constants
#define BB   2
#define SS   2048
#define MM   512
#define DD   1024
#define HH   16
#define HD   64
#define NTOK (BB*SS)        // 4096
#define MTOK (BB*MM)        // 1024
#define FF   4096           // 4*D
#define KSPLIT 4

// ---------------- scratch (device globals; no allocation) ----------------
__device__ __half g_h   [NTOK*DD];
__device__ __half g_qkv [NTOK*96];           // fused tq|ckv
__device__ float  g_part[KSPLIT*NTOK*96];    // split-K partials (fp32)
__device__ __half g_q   [NTOK*DD];
__device__ __half g_kvs [NTOK*2048];         // fused k|v
__device__ __half g_o   [NTOK*DD];
__device__ float  g_x1  [NTOK*DD];           // residual stream fp32
__device__ __half g_h2  [NTOK*DD];
__device__ __half g_qc  [NTOK*DD];
__device__ __half g_kv2 [MTOK*2048];         // fused kc|vc
__device__ __half g_oc  [NTOK*DD];
__device__ float  g_x2  [NTOK*DD];           // residual stream fp32
__device__ __half g_h3  [NTOK*DD];
__device__ __half g_act [NTOK*FF];           // silu(gate)*up (fused epilogue)
__device__ __half g_mem [MTOK*DD];

// fp16 transposed weights: Wt[N][K]
__device__ __half gw_qkv   [96*DD];
__device__ __half gw_uq    [DD*32];
__device__ __half gw_ukuv  [2048*64];
__device__ __half gw_oself [DD*DD];
__device__ __half gw_qc    [DD*DD];
__device__ __half gw_kcvc  [2048*DD];
__device__ __half gw_oc    [DD*DD];
__device__ __half gw_gateup[(2*FF)*DD];      // INTERLEAVED: row 2j=gate_j, 2j+1=up_j
__device__ __half gw_down  [DD*FF];

// ---------------- fused weight convert+transpose ----------------
struct WDesc { const float* src; __half* dst; int K; int N; int tile0; int rowMul; int rowOff; };
struct WTable { WDesc w[13]; };

__global__ void convert_all_kernel(WTable t) {
    __shared__ float tl[32][33];
    int bid = blockIdx.x;
    int wi = 0;
    #pragma unroll
    for (int i = 1; i < 13; i++) if (bid >= t.w[i].tile0) wi = i;
    const WDesc d = t.w[wi];
    int lt = bid - d.tile0;
    int ntiles_n = d.N >> 5;
    int n0 = (lt % ntiles_n) * 32;
    int k0 = (lt / ntiles_n) * 32;
    int tx = threadIdx.x & 31, ty = threadIdx.x >> 5;
    #pragma unroll
    for (int i = 0; i < 4; i++) {
        int k = k0 + ty + i * 8;
        tl[ty + i * 8][tx] = d.src[(size_t)k * d.N + n0 + tx];
    }
    __syncthreads();
    #pragma unroll
    for (int i = 0; i < 4; i++) {
        int n = n0 + ty + i * 8;
        d.dst[(size_t)(d.rowMul * n + d.rowOff) * d.K + k0 + tx] = __float2half_rn(tl[tx][ty + i * 8]);
    }
}

__global__ void round_copy_kernel(const float* __restrict__ in, __half* __restrict__ out, int n) {
    int i = blockIdx.x * blockDim.x + threadIdx.x;
    if (i < n) out[i] = __float2half_rn(in[i]);
}

// ---------------- split-K reduce for fused qkv ----------------
__global__ void reduce_qkv_kernel(const float* __restrict__ part, __half* __restrict__ qkv) {
    int i = blockIdx.x * 256 + threadIdx.x;
    float s = 0.f;
    #pragma unroll
    for (int z = 0; z < KSPLIT; z++) s += part[(size_t)z * NTOK * 96 + i];
    qkv[i] = __float2half_rn(s);
}

// ---------------- rmsnorm (fp16 out, float4 loads; D=1024, 256 thr) ----------------
__global__ void rmsnorm_kernel(const float* __restrict__ x, const float* __restrict__ w,
                               __half* __restrict__ out, int D) {
    int row = blockIdx.x;
    const float4* xr = (const float4*)(x + (size_t)row * D);
    float4 v = xr[threadIdx.x];
    __shared__ float red[256];
    float s = v.x * v.x + v.y * v.y + v.z * v.z + v.w * v.w;
    red[threadIdx.x] = s; __syncthreads();
    for (int st = 128; st > 0; st >>= 1) {
        if (threadIdx.x < st) red[threadIdx.x] += red[threadIdx.x + st];
        __syncthreads();
    }
    float inv = rsqrtf(red[0] / (float)D + 1e-6f);
    float4 wv = ((const float4*)w)[threadIdx.x];
    __half2 h0 = __floats2half2_rn(v.x * inv * wv.x, v.y * inv * wv.y);
    __half2 h1 = __floats2half2_rn(v.z * inv * wv.z, v.w * inv * wv.w);
    __half2* op = (__half2*)(out + (size_t)row * D) + threadIdx.x * 2;
    op[0] = h0; op[1] = h1;
}

// ---------------- fp16 MMA + ldmatrix helpers ----------------
__device__ __forceinline__ void mma16816h(float* c, const uint32_t* a, const uint32_t* b) {
    asm volatile(
        "mma.sync.aligned.m16n8k16.row.col.f32.f16.f16.f32 "
        "{%0,%1,%2,%3}, {%4,%5,%6,%7}, {%8,%9}, {%0,%1,%2,%3};\n"
        : "+f"(c[0]), "+f"(c[1]), "+f"(c[2]), "+f"(c[3])
        : "r"(a[0]), "r"(a[1]), "r"(a[2]), "r"(a[3]), "r"(b[0]), "r"(b[1]));
}

__device__ __forceinline__ void ldsm4(uint32_t* r, uint32_t addr) {
    asm volatile("ldmatrix.sync.aligned.m8n8.x4.shared.b16 {%0,%1,%2,%3}, [%4];"
                 : "=r"(r[0]), "=r"(r[1]), "=r"(r[2]), "=r"(r[3]) : "r"(addr));
}

__device__ __forceinline__ void ldsm4t(uint32_t* r, uint32_t addr) {
    asm volatile("ldmatrix.sync.aligned.m8n8.x4.trans.shared.b16 {%0,%1,%2,%3}, [%4];"
                 : "=r"(r[0]), "=r"(r[1]), "=r"(r[2]), "=r"(r[3]) : "r"(addr));
}

__device__ __forceinline__ void cpasync16(uint32_t dst, const void* src) {
    asm volatile("cp.async.cg.shared.global [%0], [%1], 16;\n" :: "r"(dst), "l"(src));
}

__device__ __forceinline__ float sigmoidf_(float v) { return 1.f / (1.f + __expf(-v)); }

#define LDH 40                  // smem row stride in halves (80B, conflict-free)
#define H_ST (128 * LDH)        // halves per tensor per stage (5120)
#define STG 4
#define TG_SMEM (STG * 2 * H_ST * 2)   // 81920 B

// ================ fp16 tensor GEMM: 128x128 tile, BK=32, cp.async 4-stage ====
// mode 0: Cf fp32 (+R); mode 1: Ch fp16; mode 2: fused silu-pair -> Ch fp16 [M][N/2]
__global__ __launch_bounds__(256)
void hgemm_kernel(const __half* __restrict__ A, int lda,
                  const __half* __restrict__ Wt, int ldb,
                  const float* __restrict__ R, float* __restrict__ Cf,
                  __half* __restrict__ Ch, int M, int N, int K, int mode) {
    extern __shared__ __half hsm[];
    __half* As = hsm;
    __half* Bs = hsm + STG * H_ST;

    int tid = threadIdx.x;
    int lane = tid & 31, warp = tid >> 5;
    int wm = warp & 1, wn = warp >> 1;          // 2 x 4 warps: 64 x 32 each
    int bm = blockIdx.y * 128, bn = blockIdx.x * 128;
    int kz = blockIdx.z;

    float acc[4][4][4] = {};

    int ld_row = tid >> 1;
    int gsel = (tid & 1) * 16;

    int nc = K / 32;

    const __half* aRow = A + (size_t)(bm + ld_row) * lda + kz * K + gsel;
    int nIdx = bn + ld_row;
    if (nIdx >= N) nIdx = N - 1;
    const __half* bRow = Wt + (size_t)nIdx * ldb + kz * K + gsel;
    uint32_t aD = (uint32_t)__cvta_generic_to_shared(As + ld_row * LDH + gsel);
    uint32_t bD = (uint32_t)__cvta_generic_to_shared(Bs + ld_row * LDH + gsel);

    uint32_t aBase0 = (uint32_t)__cvta_generic_to_shared(As) +
        ((uint32_t)(wm * 64 + (lane & 15)) * LDH + (uint32_t)((lane >> 4) * 8)) * 2;
    uint32_t bBase0 = (uint32_t)__cvta_generic_to_shared(Bs) +
        ((uint32_t)(wn * 32 + ((lane >> 4) << 3) + (lane & 7)) * LDH +
         (uint32_t)(((lane >> 3) & 1) * 8)) * 2;

    #pragma unroll
    for (int s = 0; s < 3; s++) {
        if (s < nc) {
            int k0 = s * 32;
            cpasync16(aD + s * H_ST * 2,      aRow + k0);
            cpasync16(aD + s * H_ST * 2 + 16, aRow + k0 + 8);
            cpasync16(bD + s * H_ST * 2,      bRow + k0);
            cpasync16(bD + s * H_ST * 2 + 16, bRow + k0 + 8);
        }
        asm volatile("cp.async.commit_group;\n" ::: "memory");
    }

    for (int c = 0; c < nc; c++) {
        int rem = nc - 1 - c;
        if (rem >= 2)      asm volatile("cp.async.wait_group 2;\n" ::: "memory");
        else if (rem == 1) asm volatile("cp.async.wait_group 1;\n" ::: "memory");
        else               asm volatile("cp.async.wait_group 0;\n" ::: "memory");
        __syncthreads();

        int pre = c + 3;
        if (pre < nc) {
            int s = pre % STG;
            int k0 = pre * 32;
            cpasync16(aD + s * H_ST * 2,      aRow + k0);
            cpasync16(aD + s * H_ST * 2 + 16, aRow + k0 + 8);
            cpasync16(bD + s * H_ST * 2,      bRow + k0);
            cpasync16(bD + s * H_ST * 2 + 16, bRow + k0 + 8);
            asm volatile("cp.async.commit_group;\n" ::: "memory");
        }

        uint32_t stOff = (uint32_t)(c % STG) * H_ST * 2;
        uint32_t aB = aBase0 + stOff;
        uint32_t bB = bBase0 + stOff;
        #pragma unroll
        for (int ks = 0; ks < 2; ks++) {
            uint32_t kOff = (uint32_t)ks * 32;
            uint32_t afr[4][4], bt[2][4];
            #pragma unroll
            for (int mt = 0; mt < 4; mt++)
                ldsm4(afr[mt], aB + (uint32_t)(mt * 16 * LDH) * 2 + kOff);
            #pragma unroll
            for (int qq = 0; qq < 2; qq++)
                ldsm4(bt[qq], bB + (uint32_t)(qq * 16 * LDH) * 2 + kOff);
            uint32_t bfr[4][2] = {{bt[0][0], bt[0][1]}, {bt[0][2], bt[0][3]},
                                  {bt[1][0], bt[1][1]}, {bt[1][2], bt[1][3]}};
            #pragma unroll
            for (int mt = 0; mt < 4; mt++)
                #pragma unroll
                for (int nt = 0; nt < 4; nt++)
                    mma16816h(acc[mt][nt], afr[mt], bfr[nt]);
        }
    }

    if (mode == 2) {
        int halfN = N >> 1;
        #pragma unroll
        for (int mt = 0; mt < 4; mt++) {
            int r0 = bm + wm * 64 + mt * 16 + (lane >> 2);
            #pragma unroll
            for (int nt = 0; nt < 4; nt++) {
                int cn = bn + wn * 32 + nt * 8 + (lane & 3) * 2;
                int j = cn >> 1;
                float g0 = acc[mt][nt][0], u0 = acc[mt][nt][1];
                float g1 = acc[mt][nt][2], u1 = acc[mt][nt][3];
                Ch[(size_t)r0 * halfN + j]       = __float2half_rn(g0 * sigmoidf_(g0) * u0);
                Ch[(size_t)(r0 + 8) * halfN + j] = __float2half_rn(g1 * sigmoidf_(g1) * u1);
            }
        }
        return;
    }

    float* Cz = Cf ? Cf + (size_t)kz * M * N : nullptr;
    #pragma unroll
    for (int mt = 0; mt < 4; mt++) {
        int r0 = bm + wm * 64 + mt * 16 + (lane >> 2);
        #pragma unroll
        for (int nt = 0; nt < 4; nt++) {
            int cn = bn + wn * 32 + nt * 8 + (lane & 3) * 2;
            if (cn < N) {
                float2 v0 = make_float2(acc[mt][nt][0], acc[mt][nt][1]);
                float2 v1 = make_float2(acc[mt][nt][2], acc[mt][nt][3]);
                if (Cz) {
                    if (R) {
                        float2 ra = *(const float2*)&R[(size_t)r0 * N + cn];
                        float2 rb = *(const float2*)&R[(size_t)(r0 + 8) * N + cn];
                        v0.x += ra.x; v0.y += ra.y;
                        v1.x += rb.x; v1.y += rb.y;
                    }
                    *(float2*)&Cz[(size_t)r0 * N + cn] = v0;
                    *(float2*)&Cz[(size_t)(r0 + 8) * N + cn] = v1;
                } else {
                    *(__half2*)&Ch[(size_t)r0 * N + cn] = __floats2half2_rn(v0.x, v0.y);
                    *(__half2*)&Ch[(size_t)(r0 + 8) * N + cn] = __floats2half2_rn(v1.x, v1.y);
                }
            }
        }
    }
}

// ---------------- self attention: Br=128, Bc=64, cp.async KV pipeline ----------------
#define QLD 72
#define ATT_HALVES (128*QLD + 128*QLD + 4*64*QLD)
#define ATT_SMEM (ATT_HALVES*2 + (128*68 + 3*128)*4)

__global__ __launch_bounds__(256)
void self_attn_kernel(const __half* __restrict__ q, const __half* __restrict__ kvs,
                      __half* __restrict__ o) {
    extern __shared__ char smc[];
    __half* Qs  = (__half*)smc;
    __half* Ph  = Qs + 128 * QLD;
    __half* KV0 = Ph + 128 * QLD;
    float*  Ps  = (float*)(KV0 + 4 * 64 * QLD);
    float* row_max  = Ps + 128 * 68;
    float* row_sum  = row_max + 128;
    float* row_corr = row_sum + 128;

    int qt = blockIdx.x, h = blockIdx.y, b = blockIdx.z;
    int q0 = qt * 128;
    int tid = threadIdx.x;
    int lane = tid & 31, warp = tid >> 5;
    int wm = warp >> 1, wn = warp & 1;

    uint32_t qsS  = (uint32_t)__cvta_generic_to_shared(Qs);
    uint32_t kv0S = (uint32_t)__cvta_generic_to_shared(KV0);

    uint32_t qBase = qsS +
        ((uint32_t)(wm * 32 + (lane & 15)) * QLD + (uint32_t)((lane >> 4) * 8)) * 2;
    uint32_t pBase = (uint32_t)__cvta_generic_to_shared(Ph) +
        ((uint32_t)(wm * 32 + (lane & 15)) * QLD + (uint32_t)((lane >> 4) * 8)) * 2;
    uint32_t kBaseC = ((uint32_t)(wn * 32 + ((lane >> 4) << 3) + (lane & 7)) * QLD +
                       (uint32_t)(((lane >> 3) & 1) * 8)) * 2;
    uint32_t vBaseC = ((uint32_t)(lane & 15) * QLD +
                       (uint32_t)(wn * 32 + (lane >> 4) * 8)) * 2;

    const __half* qg = q + ((size_t)(b * SS + q0)) * DD + h * HD;
    #pragma unroll
    for (int i = 0; i < 4; i++) {
        int cid = i * 256 + tid;
        int r = cid >> 3, u = cid & 7;
        cpasync16(qsS + ((uint32_t)r * QLD + u * 8) * 2, qg + (size_t)r * DD + u * 8);
    }
    {
        const __half* kg = kvs + ((size_t)(b * SS)) * 2048 + h * HD;
        #pragma unroll
        for (int i = 0; i < 2; i++) {
            int cid = i * 256 + tid;
            int r = cid >> 3, u = cid & 7;
            const __half* src = kg + (size_t)r * 2048 + u * 8;
            uint32_t d = ((uint32_t)r * QLD + u * 8) * 2;
            cpasync16(kv0S + d, src);
            cpasync16(kv0S + (64 * QLD) * 2 + d, src + 1024);
        }
    }
    asm volatile("cp.async.commit_group;\n" ::: "memory");

    if (tid < 128) { row_max[tid] = -INFINITY; row_sum[tid] = 0.f; }
    float oacc[2][4][4] = {};

    int jmax = 2 * qt + 1;
    for (int jt = 0; jt <= jmax; jt++) {
        int cur = jt & 1;
        bool pf = (jt + 1 <= jmax);
        if (pf) {
            int kvn = (jt + 1) * 64;
            int nst = (jt + 1) & 1;
            uint32_t stB = kv0S + (uint32_t)(nst * 2 * 64 * QLD) * 2;
            const __half* kg = kvs + ((size_t)(b * SS + kvn)) * 2048 + h * HD;
            #pragma unroll
            for (int i = 0; i < 2; i++) {
                int cid = i * 256 + tid;
                int r = cid >> 3, u = cid & 7;
                const __half* src = kg + (size_t)r * 2048 + u * 8;
                uint32_t d = ((uint32_t)r * QLD + u * 8) * 2;
                cpasync16(stB + d, src);
                cpasync16(stB + (64 * QLD) * 2 + d, src + 1024);
            }
            asm volatile("cp.async.commit_group;\n" ::: "memory");
            asm volatile("cp.async.wait_group 1;\n" ::: "memory");
        } else {
            asm volatile("cp.async.wait_group 0;\n" ::: "memory");
        }
        __syncthreads();

        uint32_t stOff = (uint32_t)(cur * 2 * 64 * QLD) * 2;
        uint32_t kB = kv0S + stOff + kBaseC;
        uint32_t vB = kv0S + stOff + (64 * QLD) * 2 + vBaseC;
        int kv0 = jt * 64;

        float sacc[2][4][4] = {};
        #pragma unroll
        for (int ks = 0; ks < 4; ks++) {
            uint32_t kOff = (uint32_t)ks * 32;
            uint32_t afr[2][4], bt[2][4];
            #pragma unroll
            for (int mt = 0; mt < 2; mt++)
                ldsm4(afr[mt], qBase + (uint32_t)(mt * 16 * QLD) * 2 + kOff);
            #pragma unroll
            for (int qq = 0; qq < 2; qq++)
                ldsm4(bt[qq], kB + (uint32_t)(qq * 16 * QLD) * 2 + kOff);
            uint32_t bfr[4][2] = {{bt[0][0], bt[0][1]}, {bt[0][2], bt[0][3]},
                                  {bt[1][0], bt[1][1]}, {bt[1][2], bt[1][3]}};
            #pragma unroll
            for (int mt = 0; mt < 2; mt++)
                #pragma unroll
                for (int nt = 0; nt < 4; nt++)
                    mma16816h(sacc[mt][nt], afr[mt], bfr[nt]);
        }
        bool diag = (jt >= 2 * qt);
        #pragma unroll
        for (int mt = 0; mt < 2; mt++) {
            int lr0 = wm * 32 + mt * 16 + (lane >> 2);
            #pragma unroll
            for (int nt = 0; nt < 4; nt++) {
                int lc0 = wn * 32 + nt * 8 + (lane & 3) * 2;
                #pragma unroll
                for (int e = 0; e < 4; e++) {
                    int lr = lr0 + (e >> 1) * 8;
                    int lc = lc0 + (e & 1);
                    float sv = sacc[mt][nt][e] * 0.125f;
                    if (diag && (kv0 + lc > q0 + lr)) sv = -INFINITY;
                    Ps[lr * 68 + lc] = sv;
                }
            }
        }
        __syncthreads();

        {
            int srow = tid >> 1, sseg = tid & 1;
            float* pr = Ps + srow * 68 + sseg * 32;
            __half* ph = Ph + srow * QLD + sseg * 32;
            float m0 = row_max[srow];
            float tm = -INFINITY;
            #pragma unroll
            for (int c = 0; c < 32; c++) tm = fmaxf(tm, pr[c]);
            tm = fmaxf(tm, __shfl_xor_sync(0xffffffff, tm, 1));
            float nm = fmaxf(m0, tm);
            float s = 0.f;
            #pragma unroll
            for (int c = 0; c < 32; c++) {
                float p = __expf(pr[c] - nm);
                ph[c] = __float2half_rn(p);
                s += p;
            }
            s += __shfl_xor_sync(0xffffffff, s, 1);
            if (sseg == 0) {
                float corr = __expf(m0 - nm);
                row_sum[srow]  = row_sum[srow] * corr + s;
                row_max[srow]  = nm;
                row_corr[srow] = corr;
            }
        }
        __syncthreads();

        #pragma unroll
        for (int mt = 0; mt < 2; mt++) {
            int r0 = wm * 32 + mt * 16 + (lane >> 2);
            float c0 = row_corr[r0], c1 = row_corr[r0 + 8];
            #pragma unroll
            for (int nt = 0; nt < 4; nt++) {
                oacc[mt][nt][0] *= c0; oacc[mt][nt][1] *= c0;
                oacc[mt][nt][2] *= c1; oacc[mt][nt][3] *= c1;
            }
        }
        #pragma unroll
        for (int ks = 0; ks < 4; ks++) {
            uint32_t afr[2][4], bt[2][4];
            #pragma unroll
            for (int mt = 0; mt < 2; mt++)
                ldsm4(afr[mt], pBase + (uint32_t)(mt * 16 * QLD) * 2 + (uint32_t)ks * 32);
            #pragma unroll
            for (int qq = 0; qq < 2; qq++)
                ldsm4t(bt[qq], vB + (uint32_t)(ks * 16 * QLD) * 2 + (uint32_t)qq * 32);
            uint32_t bfr[4][2] = {{bt[0][0], bt[0][1]}, {bt[0][2], bt[0][3]},
                                  {bt[1][0], bt[1][1]}, {bt[1][2], bt[1][3]}};
            #pragma unroll
            for (int mt = 0; mt < 2; mt++)
                #pragma unroll
                for (int nt = 0; nt < 4; nt++)
                    mma16816h(oacc[mt][nt], afr[mt], bfr[nt]);
        }
        __syncthreads();
    }

    #pragma unroll
    for (int mt = 0; mt < 2; mt++) {
        int r0 = wm * 32 + mt * 16 + (lane >> 2);
        float i0 = 1.f / row_sum[r0], i1 = 1.f / row_sum[r0 + 8];
        #pragma unroll
        for (int nt = 0; nt < 4; nt++) {
            int c0 = wn * 32 + nt * 8 + (lane & 3) * 2;
            size_t ra = ((size_t)(b * SS + q0 + r0)) * DD + h * HD + c0;
            size_t rb = ((size_t)(b * SS + q0 + r0 + 8)) * DD + h * HD + c0;
            *(__half2*)&o[ra] = __floats2half2_rn(oacc[mt][nt][0] * i0, oacc[mt][nt][1] * i0);
            *(__half2*)&o[rb] = __floats2half2_rn(oacc[mt][nt][2] * i1, oacc[mt][nt][3] * i1);
        }
    }
}

// ---------------- cross attention (windowed, <=9 keys): 1 block = 1 token, 16 warps ----
__global__ __launch_bounds__(512)
void cross_attn_kernel(const __half* __restrict__ qc, const __half* __restrict__ kv2,
                       const int* __restrict__ seg_ids, __half* __restrict__ oc) {
    int n = blockIdx.x;
    int warp = threadIdx.x >> 5;        // = head
    int lane = threadIdx.x & 31;
    int h = warp;
    int b = n / SS;
    int seg = seg_ids[n];
    int jlo = seg - 8; if (jlo < 0) jlo = 0;
    int cnt = seg - jlo + 1;

    const __half* qv = qc + (size_t)n * DD + h * HD;
    float q0v = __half2float(qv[lane]), q1v = __half2float(qv[lane + 32]);

    float sc[9];
    float mx = -INFINITY;
    for (int t = 0; t < cnt; t++) {
        const __half* kv = kv2 + ((size_t)(b * MM + jlo + t)) * 2048 + h * HD;
        float p = q0v * __half2float(kv[lane]) + q1v * __half2float(kv[lane + 32]);
        #pragma unroll
        for (int off = 16; off > 0; off >>= 1)
            p += __shfl_xor_sync(0xffffffff, p, off);
        p *= 0.125f;
        sc[t] = p;
        mx = fmaxf(mx, p);
    }
    float sum = 0.f;
    for (int t = 0; t < cnt; t++) { sc[t] = __expf(sc[t] - mx); sum += sc[t]; }
    float o0 = 0.f, o1 = 0.f;
    for (int t = 0; t < cnt; t++) {
        const __half* vv = kv2 + ((size_t)(b * MM + jlo + t)) * 2048 + 1024 + h * HD;
        o0 += sc[t] * __half2float(vv[lane]);
        o1 += sc[t] * __half2float(vv[lane + 32]);
    }
    float inv = 1.f / sum;
    oc[(size_t)n * DD + h * HD + lane]      = __float2half_rn(o0 * inv);
    oc[(size_t)n * DD + h * HD + lane + 32] = __float2half_rn(o1 * inv);
}

// ---------------- launch ----------------
extern "C" void kernel_launch(void* const* d_in, const int* in_sizes, int n_in,
                              void* d_out, int out_size) {
    const float* x        = (const float*)d_in[0];
    const float* memory   = (const float*)d_in[1];
    const int*   seg_ids  = (const int*)  d_in[2];
    const float* norm1_w  = (const float*)d_in[3];
    const float* W_dq     = (const float*)d_in[4];
    const float* W_uq     = (const float*)d_in[5];
    const float* W_dkv    = (const float*)d_in[6];
    const float* W_uk     = (const float*)d_in[7];
    const float* W_uv     = (const float*)d_in[8];
    const float* W_o_self = (const float*)d_in[9];
    const float* norm2_w  = (const float*)d_in[10];
    const float* W_q_c    = (const float*)d_in[11];
    const float* W_k_c    = (const float*)d_in[12];
    const float* W_v_c    = (const float*)d_in[13];
    const float* W_o_c    = (const float*)d_in[14];
    const float* norm3_w  = (const float*)d_in[15];
    const float* W_gate   = (const float*)d_in[16];
    const float* W_up     = (const float*)d_in[17];
    const float* W_down   = (const float*)d_in[18];
    float* out = (float*)d_out;

    __half *h, *qkv, *q, *kvs, *o, *h2, *qc, *kv2, *oc, *h3, *act, *mem;
    float *part, *x1, *x2;
    cudaGetSymbolAddress((void**)&h,    g_h);
    cudaGetSymbolAddress((void**)&qkv,  g_qkv);
    cudaGetSymbolAddress((void**)&part, g_part);
    cudaGetSymbolAddress((void**)&q,    g_q);
    cudaGetSymbolAddress((void**)&kvs,  g_kvs);
    cudaGetSymbolAddress((void**)&o,    g_o);
    cudaGetSymbolAddress((void**)&x1,   g_x1);
    cudaGetSymbolAddress((void**)&h2,   g_h2);
    cudaGetSymbolAddress((void**)&qc,   g_qc);
    cudaGetSymbolAddress((void**)&kv2,  g_kv2);
    cudaGetSymbolAddress((void**)&oc,   g_oc);
    cudaGetSymbolAddress((void**)&x2,   g_x2);
    cudaGetSymbolAddress((void**)&h3,   g_h3);
    cudaGetSymbolAddress((void**)&act,  g_act);
    cudaGetSymbolAddress((void**)&mem,  g_mem);

    __half *w_qkv, *w_uq, *w_ukuv, *w_oself, *w_qc, *w_kcvc, *w_oc, *w_gateup, *w_down;
    cudaGetSymbolAddress((void**)&w_qkv,    gw_qkv);
    cudaGetSymbolAddress((void**)&w_uq,     gw_uq);
    cudaGetSymbolAddress((void**)&w_ukuv,   gw_ukuv);
    cudaGetSymbolAddress((void**)&w_oself,  gw_oself);
    cudaGetSymbolAddress((void**)&w_qc,     gw_qc);
    cudaGetSymbolAddress((void**)&w_kcvc,   gw_kcvc);
    cudaGetSymbolAddress((void**)&w_oc,     gw_oc);
    cudaGetSymbolAddress((void**)&w_gateup, gw_gateup);
    cudaGetSymbolAddress((void**)&w_down,   gw_down);

    WTable wt;
    const float* srcs[13] = {W_dq, W_uq, W_dkv, W_uk, W_uv, W_o_self, W_q_c, W_k_c, W_v_c,
                             W_o_c, W_gate, W_up, W_down};
    __half* dsts[13] = {w_qkv, w_uq, w_qkv + 32 * DD, w_ukuv, w_ukuv + 1024 * 64, w_oself, w_qc,
                        w_kcvc, w_kcvc + 1024 * DD, w_oc, w_gateup, w_gateup, w_down};
    int Ks[13]  = {DD, 32, DD, 64, 64, DD, DD, DD, DD, DD, DD, DD, FF};
    int Ns[13]  = {32, DD, 64, DD, DD, DD, DD, DD, DD, DD, FF, FF, DD};
    int rm[13]  = {1, 1, 1, 1, 1, 1, 1, 1, 1, 1, 2, 2, 1};
    int ro[13]  = {0, 0, 0, 0, 0, 0, 0, 0, 0, 0, 0, 1, 0};
    int tot = 0;
    for (int i = 0; i < 13; i++) {
        wt.w[i].src = srcs[i]; wt.w[i].dst = dsts[i];
        wt.w[i].K = Ks[i]; wt.w[i].N = Ns[i];
        wt.w[i].tile0 = tot;
        wt.w[i].rowMul = rm[i]; wt.w[i].rowOff = ro[i];
        tot += (Ks[i] / 32) * (Ns[i] / 32);
    }
    convert_all_kernel<<<tot, 256>>>(wt);
    round_copy_kernel<<<(MTOK * DD + 255) / 256, 256>>>(memory, mem, MTOK * DD);

    cudaFuncSetAttribute(hgemm_kernel, cudaFuncAttributeMaxDynamicSharedMemorySize, TG_SMEM);
    cudaFuncSetAttribute(self_attn_kernel, cudaFuncAttributeMaxDynamicSharedMemorySize, ATT_SMEM);

    // ---- Phase 1: MLA self-attention ----
    rmsnorm_kernel<<<NTOK, 256>>>(x, norm1_w, h, DD);
    hgemm_kernel<<<dim3(1, NTOK / 128, KSPLIT), 256, TG_SMEM>>>(h, DD, w_qkv, DD, nullptr, part,
                                                                nullptr, NTOK, 96, DD / KSPLIT, 0);
    reduce_qkv_kernel<<<NTOK * 96 / 256, 256>>>(part, qkv);
    hgemm_kernel<<<dim3(DD / 128, NTOK / 128), 256, TG_SMEM>>>(qkv, 96, w_uq, 32, nullptr, nullptr,
                                                               q, NTOK, DD, 32, 1);
    hgemm_kernel<<<dim3(2048 / 128, NTOK / 128), 256, TG_SMEM>>>(qkv + 32, 96, w_ukuv, 64, nullptr,
                                                                 nullptr, kvs, NTOK, 2048, 64, 1);
    self_attn_kernel<<<dim3(SS / 128, HH, BB), 256, ATT_SMEM>>>(q, kvs, o);
    hgemm_kernel<<<dim3(DD / 128, NTOK / 128), 256, TG_SMEM>>>(o, DD, w_oself, DD, x, x1,
                                                               nullptr, NTOK, DD, DD, 0);

    // ---- Phase 2: windowed cross-attention ----
    rmsnorm_kernel<<<NTOK, 256>>>(x1, norm2_w, h2, DD);
    hgemm_kernel<<<dim3(DD / 128, NTOK / 128), 256, TG_SMEM>>>(h2, DD, w_qc, DD, nullptr, nullptr,
                                                               qc, NTOK, DD, DD, 1);
    hgemm_kernel<<<dim3(2048 / 128, MTOK / 128), 256, TG_SMEM>>>(mem, DD, w_kcvc, DD, nullptr,
                                                                 nullptr, kv2, MTOK, 2048, DD, 1);
    cross_attn_kernel<<<NTOK, 512>>>(qc, kv2, seg_ids, oc);
    hgemm_kernel<<<dim3(DD / 128, NTOK / 128), 256, TG_SMEM>>>(oc, DD, w_oc, DD, x1, x2,
                                                               nullptr, NTOK, DD, DD, 0);

    // ---- Phase 3: SwiGLU MLP (silu fused into gate/up GEMM epilogue) ----
    rmsnorm_kernel<<<NTOK, 256>>>(x2, norm3_w, h3, DD);
    hgemm_kernel<<<dim3((2 * FF) / 128, NTOK / 128), 256, TG_SMEM>>>(h3, DD, w_gateup, DD, nullptr,
                                                                     nullptr, act, NTOK, 2 * FF, DD, 2);
    hgemm_kernel<<<dim3(DD / 128, NTOK / 128), 256, TG_SMEM>>>(act, FF, w_down, FF, x2, out,
                                                               nullptr, NTOK, DD, FF, 0);
}